// round 1
// baseline (speedup 1.0000x reference)
#include <cuda_runtime.h>
#include <cstdint>

// Problem constants (B,H,S,D) = (4,16,2048,64)
#define B_ 4
#define H_ 16
#define S_ 2048
#define D_ 64
#define BR 64          // query rows per CTA
#define BC 64          // key cols per tile
#define STRIDE 68      // smem row stride (floats): 68%32==4 -> conflict-free frag reads
#define NWARP 4

__device__ __forceinline__ uint32_t f2tf(float x) {
    uint32_t r;
    asm("cvt.rna.tf32.f32 %0, %1;" : "=r"(r) : "f"(x));
    return r;
}

__device__ __forceinline__ void mma_tf32(float* c, const uint32_t* a, uint32_t b0, uint32_t b1) {
    asm volatile(
        "mma.sync.aligned.m16n8k8.row.col.f32.tf32.tf32.f32 "
        "{%0,%1,%2,%3},{%4,%5,%6,%7},{%8,%9},{%0,%1,%2,%3};"
        : "+f"(c[0]), "+f"(c[1]), "+f"(c[2]), "+f"(c[3])
        : "r"(a[0]), "r"(a[1]), "r"(a[2]), "r"(a[3]), "r"(b0), "r"(b1));
}

__global__ __launch_bounds__(128, 1)
void fa_tf32_kernel(const float* __restrict__ Q,
                    const float* __restrict__ K,
                    const float* __restrict__ V,
                    const int* __restrict__ to_mask,
                    float* __restrict__ O) {
    __shared__ __align__(16) float bufK[BR * STRIDE];  // K tile, later reused for P
    __shared__ __align__(16) float bufV[BR * STRIDE];  // V tile

    const int qt   = blockIdx.x;          // query tile (0..31)
    const int bh   = blockIdx.y;          // fused batch*head (0..63)
    const int tid  = threadIdx.x;
    const int w    = tid >> 5;
    const int lane = tid & 31;
    const int g    = lane >> 2;           // groupID (0..7)
    const int t    = lane & 3;            // threadID in group (0..3)
    const int msk  = to_mask[0];

    const float* Qb = Q + ((size_t)bh * S_ + (size_t)qt * BR) * D_;
    const float* Kb = K + (size_t)bh * S_ * D_;
    const float* Vb = V + (size_t)bh * S_ * D_;

    // ---- load Q tile (64x64 f32) into bufK, then build A fragments in regs ----
    #pragma unroll
    for (int i = 0; i < 8; i++) {
        int idx = tid + i * 128;          // float4 index in [0,1024)
        int row = idx >> 4, c4 = idx & 15;
        float4 v = *reinterpret_cast<const float4*>(Qb + row * D_ + c4 * 4);
        *reinterpret_cast<float4*>(&bufK[row * STRIDE + c4 * 4]) = v;
    }
    __syncthreads();

    uint32_t qa[8][4];                    // Q fragments, scale 1/sqrt(64) folded in
    {
        const int r0 = w * 16 + g;
        #pragma unroll
        for (int kk = 0; kk < 8; kk++) {
            qa[kk][0] = f2tf(0.125f * bufK[r0 * STRIDE + kk * 8 + t]);
            qa[kk][1] = f2tf(0.125f * bufK[(r0 + 8) * STRIDE + kk * 8 + t]);
            qa[kk][2] = f2tf(0.125f * bufK[r0 * STRIDE + kk * 8 + t + 4]);
            qa[kk][3] = f2tf(0.125f * bufK[(r0 + 8) * STRIDE + kk * 8 + t + 4]);
        }
    }
    __syncthreads();

    float o[8][4];                        // output accumulators (16 x 64 per warp)
    #pragma unroll
    for (int nt = 0; nt < 8; nt++) { o[nt][0] = 0.f; o[nt][1] = 0.f; o[nt][2] = 0.f; o[nt][3] = 0.f; }
    float m0 = -1e30f, m1 = -1e30f;       // row maxes (row g, row g+8)
    float l0 = 0.f, l1 = 0.f;             // per-thread partial row sums

    const int ntiles = msk ? (qt + 1) : (S_ / BC);

    for (int j = 0; j < ntiles; j++) {
        // ---- load K, V tiles to smem ----
        #pragma unroll
        for (int i = 0; i < 8; i++) {
            int idx = tid + i * 128;
            int row = idx >> 4, c4 = idx & 15;
            *reinterpret_cast<float4*>(&bufK[row * STRIDE + c4 * 4]) =
                *reinterpret_cast<const float4*>(Kb + ((size_t)(j * BC + row)) * D_ + c4 * 4);
            *reinterpret_cast<float4*>(&bufV[row * STRIDE + c4 * 4]) =
                *reinterpret_cast<const float4*>(Vb + ((size_t)(j * BC + row)) * D_ + c4 * 4);
        }
        __syncthreads();

        // ---- S = (Q/8) K^T  (16 x 64 per warp) ----
        float s[8][4];
        #pragma unroll
        for (int nt = 0; nt < 8; nt++) { s[nt][0] = 0.f; s[nt][1] = 0.f; s[nt][2] = 0.f; s[nt][3] = 0.f; }
        #pragma unroll
        for (int nt = 0; nt < 8; nt++) {
            #pragma unroll
            for (int kk = 0; kk < 8; kk++) {
                uint32_t b0 = f2tf(bufK[(nt * 8 + g) * STRIDE + kk * 8 + t]);
                uint32_t b1 = f2tf(bufK[(nt * 8 + g) * STRIDE + kk * 8 + t + 4]);
                mma_tf32(s[nt], qa[kk], b0, b1);
            }
        }
        __syncthreads();   // all warps done reading K before P overwrites bufK

        // ---- causal mask (only on the diagonal tile) ----
        if (msk && j == qt) {
            const int row0 = qt * BR + w * 16 + g;
            #pragma unroll
            for (int nt = 0; nt < 8; nt++) {
                int col = j * BC + nt * 8 + 2 * t;
                if (col     > row0)     s[nt][0] = -1e30f;
                if (col + 1 > row0)     s[nt][1] = -1e30f;
                if (col     > row0 + 8) s[nt][2] = -1e30f;
                if (col + 1 > row0 + 8) s[nt][3] = -1e30f;
            }
        }

        // ---- online softmax ----
        float tm0 = -1e30f, tm1 = -1e30f;
        #pragma unroll
        for (int nt = 0; nt < 8; nt++) {
            tm0 = fmaxf(tm0, fmaxf(s[nt][0], s[nt][1]));
            tm1 = fmaxf(tm1, fmaxf(s[nt][2], s[nt][3]));
        }
        #pragma unroll
        for (int off = 1; off < 4; off <<= 1) {
            tm0 = fmaxf(tm0, __shfl_xor_sync(0xffffffffu, tm0, off));
            tm1 = fmaxf(tm1, __shfl_xor_sync(0xffffffffu, tm1, off));
        }
        const float mn0 = fmaxf(m0, tm0), mn1 = fmaxf(m1, tm1);
        const float c0 = __expf(m0 - mn0), c1 = __expf(m1 - mn1);
        float ps0 = 0.f, ps1 = 0.f;
        #pragma unroll
        for (int nt = 0; nt < 8; nt++) {
            s[nt][0] = __expf(s[nt][0] - mn0);
            s[nt][1] = __expf(s[nt][1] - mn0);
            s[nt][2] = __expf(s[nt][2] - mn1);
            s[nt][3] = __expf(s[nt][3] - mn1);
            ps0 += s[nt][0] + s[nt][1];
            ps1 += s[nt][2] + s[nt][3];
        }
        l0 = l0 * c0 + ps0;  l1 = l1 * c1 + ps1;
        m0 = mn0;            m1 = mn1;
        #pragma unroll
        for (int nt = 0; nt < 8; nt++) {
            o[nt][0] *= c0; o[nt][1] *= c0; o[nt][2] *= c1; o[nt][3] *= c1;
        }

        // ---- write P into bufK (warp-private 16-row region), then O += P V ----
        {
            const int r0 = w * 16 + g;
            #pragma unroll
            for (int nt = 0; nt < 8; nt++) {
                bufK[r0 * STRIDE + nt * 8 + 2 * t]           = s[nt][0];
                bufK[r0 * STRIDE + nt * 8 + 2 * t + 1]       = s[nt][1];
                bufK[(r0 + 8) * STRIDE + nt * 8 + 2 * t]     = s[nt][2];
                bufK[(r0 + 8) * STRIDE + nt * 8 + 2 * t + 1] = s[nt][3];
            }
        }
        __syncwarp();

        {
            const int r0 = w * 16 + g;
            #pragma unroll
            for (int kk = 0; kk < 8; kk++) {
                uint32_t a[4];
                a[0] = f2tf(bufK[r0 * STRIDE + kk * 8 + t]);
                a[1] = f2tf(bufK[(r0 + 8) * STRIDE + kk * 8 + t]);
                a[2] = f2tf(bufK[r0 * STRIDE + kk * 8 + t + 4]);
                a[3] = f2tf(bufK[(r0 + 8) * STRIDE + kk * 8 + t + 4]);
                #pragma unroll
                for (int nt = 0; nt < 8; nt++) {
                    uint32_t b0 = f2tf(bufV[(kk * 8 + t) * STRIDE + nt * 8 + g]);
                    uint32_t b1 = f2tf(bufV[(kk * 8 + t + 4) * STRIDE + nt * 8 + g]);
                    mma_tf32(o[nt], a, b0, b1);
                }
            }
        }
        __syncthreads();   // P (bufK) and V fully consumed before next tile load
    }

    // ---- epilogue: finish row sums, normalize, store ----
    #pragma unroll
    for (int off = 1; off < 4; off <<= 1) {
        l0 += __shfl_xor_sync(0xffffffffu, l0, off);
        l1 += __shfl_xor_sync(0xffffffffu, l1, off);
    }
    const float inv0 = 1.f / l0, inv1 = 1.f / l1;
    const int row0 = qt * BR + w * 16 + g;
    float* Ob = O + (size_t)bh * S_ * D_;
    #pragma unroll
    for (int nt = 0; nt < 8; nt++) {
        int col = nt * 8 + 2 * t;
        *reinterpret_cast<float2*>(Ob + (size_t)row0 * D_ + col) =
            make_float2(o[nt][0] * inv0, o[nt][1] * inv0);
        *reinterpret_cast<float2*>(Ob + (size_t)(row0 + 8) * D_ + col) =
            make_float2(o[nt][2] * inv1, o[nt][3] * inv1);
    }
}

extern "C" void kernel_launch(void* const* d_in, const int* in_sizes, int n_in,
                              void* d_out, int out_size) {
    const float* Q = (const float*)d_in[0];
    const float* K = (const float*)d_in[1];
    const float* V = (const float*)d_in[2];
    const int* msk = (const int*)d_in[3];
    float* O = (float*)d_out;

    dim3 grid(S_ / BR, B_ * H_);
    dim3 block(128);
    fa_tf32_kernel<<<grid, block>>>(Q, K, V, msk, O);
}